// round 7
// baseline (speedup 1.0000x reference)
#include <cuda_runtime.h>
#include <cuda_bf16.h>

// Damping_27066883900008 R7: 1 row/thread @ <=64 regs for 2x occupancy
// (FFMA2 is half-rate, so 2-rows/thread had no MAC-rate edge; weights on the
// uniform LDCU port make refetch free). Constant-bank weights, f32x2 {d,o}
// net packing, MUFU.TANH.

#define NTHREADS 256
typedef unsigned long long ull;

struct __align__(16) Params {
    ull   w2p[256];    // (16,16) packed {wd2, wo2}, 16B-aligned pairs
    ull   w1p[32];     // (2,16)  packed {wd1, wo1}
    ull   b1p[16];     // {bd1, bo1}
    ull   b2p[16];     // {bd2, bo2}
    float wd3[32];     // (16,2)
    float wo3[16];     // (16,1)
    float bd3[2];
    float bo3[2];      // [1] pad
};

__device__    Params g_pack;
__constant__  Params c_p;

__device__ __forceinline__ ull pack2(float lo, float hi) {
    ull r; asm("mov.b64 %0, {%1, %2};" : "=l"(r) : "f"(lo), "f"(hi)); return r;
}
__device__ __forceinline__ void unpack2(ull v, float& lo, float& hi) {
    asm("mov.b64 {%0, %1}, %2;" : "=f"(lo), "=f"(hi) : "l"(v));
}
__device__ __forceinline__ ull fma2(ull a, ull b, ull c) {
    ull d; asm("fma.rn.f32x2 %0, %1, %2, %3;" : "=l"(d) : "l"(a), "l"(b), "l"(c)); return d;
}
__device__ __forceinline__ float tanh_ap(float x) {
    float y; asm("tanh.approx.f32 %0, %1;" : "=f"(y) : "f"(x)); return y;
}
__device__ __forceinline__ ull tanh2(ull v) {
    float lo, hi; unpack2(v, lo, hi);
    return pack2(tanh_ap(lo), tanh_ap(hi));
}

__global__ void pack_kernel(
    const float* __restrict__ w_d1, const float* __restrict__ w_d2,
    const float* __restrict__ w_d3, const float* __restrict__ w_o1,
    const float* __restrict__ w_o2, const float* __restrict__ w_o3,
    const float* __restrict__ b_d1, const float* __restrict__ b_d2,
    const float* __restrict__ b_d3, const float* __restrict__ b_o1,
    const float* __restrict__ b_o2, const float* __restrict__ b_o3)
{
    const int t = threadIdx.x;
    if (t < 256) g_pack.w2p[t] = pack2(w_d2[t], w_o2[t]);
    if (t < 32)  { g_pack.w1p[t] = pack2(w_d1[t], w_o1[t]); g_pack.wd3[t] = w_d3[t]; }
    if (t < 16)  {
        g_pack.b1p[t] = pack2(b_d1[t], b_o1[t]);
        g_pack.b2p[t] = pack2(b_d2[t], b_o2[t]);
        g_pack.wo3[t] = w_o3[t];
    }
    if (t < 2)   g_pack.bd3[t] = b_d3[t];
    if (t == 0)  { g_pack.bo3[0] = b_o3[0]; g_pack.bo3[1] = 0.0f; }
}

__global__ __launch_bounds__(NTHREADS, 4) void damping_kernel(
    const float2* __restrict__ x, float2* __restrict__ out, int nrows)
{
    const int r = blockIdx.x * NTHREADS + threadIdx.x;
    if (r >= nrows) return;

    const float2 xi = x[r];
    const ull x0p = pack2(xi.x, xi.x);
    const ull x1p = pack2(xi.y, xi.y);

    // ---------------- fused layer-1 + layer-2 (packed {d,o}) ----------------
    ull acc[16];
    #pragma unroll
    for (int j = 0; j < 16; j++) acc[j] = c_p.b2p[j];

    #pragma unroll
    for (int k = 0; k < 16; k++) {
        const ull h = tanh2(fma2(x0p, c_p.w1p[k],
                            fma2(x1p, c_p.w1p[16 + k], c_p.b1p[k])));
        #pragma unroll
        for (int j2 = 0; j2 < 8; j2++) {
            // 16B-aligned pair -> LDCU.128
            const ulonglong2 w =
                *reinterpret_cast<const ulonglong2*>(&c_p.w2p[k * 16 + j2 * 2]);
            acc[j2 * 2 + 0] = fma2(h, w.x, acc[j2 * 2 + 0]);
            acc[j2 * 2 + 1] = fma2(h, w.y, acc[j2 * 2 + 1]);
        }
    }

    // ---------------- layer 3 (scalar, nets diverge) ----------------
    float d30 = c_p.bd3[0], d31 = c_p.bd3[1], c = c_p.bo3[0];
    #pragma unroll
    for (int k = 0; k < 16; k++) {
        float pd, po; unpack2(acc[k], pd, po);
        const float gd = tanh_ap(pd);
        const float go = tanh_ap(po);
        d30 = fmaf(gd, c_p.wd3[k * 2 + 0], d30);
        d31 = fmaf(gd, c_p.wd3[k * 2 + 1], d31);
        c   = fmaf(go, c_p.wo3[k], c);
    }

    // ---------------- damping-matrix epilogue ----------------
    const float a = (fmaxf(d30, 0.0f) + 0.001f) * xi.x;
    const float b = (fmaxf(d31, 0.0f) + 0.001f) * xi.y;
    const float ac = a * c;
    float2 o;
    o.x = fmaf(a * a, xi.x, ac * xi.y);
    o.y = fmaf(ac, xi.x, fmaf(c, c, b * b) * xi.y);
    out[r] = o;
}

extern "C" void kernel_launch(void* const* d_in, const int* in_sizes, int n_in,
                              void* d_out, int out_size) {
    const float2* x   = (const float2*)d_in[0];
    const float* w_d1 = (const float*)d_in[1];
    const float* w_d2 = (const float*)d_in[2];
    const float* w_d3 = (const float*)d_in[3];
    const float* w_o1 = (const float*)d_in[4];
    const float* w_o2 = (const float*)d_in[5];
    const float* w_o3 = (const float*)d_in[6];
    const float* b_d1 = (const float*)d_in[7];
    const float* b_d2 = (const float*)d_in[8];
    const float* b_d3 = (const float*)d_in[9];
    const float* b_o1 = (const float*)d_in[10];
    const float* b_o2 = (const float*)d_in[11];
    const float* b_o3 = (const float*)d_in[12];
    float2* out = (float2*)d_out;

    pack_kernel<<<1, 256>>>(w_d1, w_d2, w_d3, w_o1, w_o2, w_o3,
                            b_d1, b_d2, b_d3, b_o1, b_o2, b_o3);

    void* src = nullptr;
    cudaGetSymbolAddress(&src, g_pack);
    cudaMemcpyToSymbolAsync(c_p, src, sizeof(Params), 0,
                            cudaMemcpyDeviceToDevice, 0);

    const int nrows = in_sizes[0] / 2;
    const int grid  = (nrows + NTHREADS - 1) / NTHREADS;
    damping_kernel<<<grid, NTHREADS>>>(x, out, nrows);
}